// round 3
// baseline (speedup 1.0000x reference)
#include <cuda_runtime.h>

#define NN 100000
#define EE 400000
#define HIDDEN 128
#define HD 256

// ---------------- device scratch (allocation-free rule: __device__ globals) ----------------
__device__ float    g_h[(size_t)NN * HIDDEN];   // x + memory
__device__ float    g_q[(size_t)NN * HD];
__device__ float    g_k[(size_t)NN * HD];
__device__ float    g_v[(size_t)NN * HD];
__device__ float    g_out[(size_t)NN * HD];     // skip-GEMM result, then += attention agg
__device__ float    g_A[(size_t)NN * HIDDEN];   // out @ W1[0:256] + b1
__device__ float    g_B[(size_t)NN * HIDDEN];   // out @ W1[256:512]
__device__ float    g_e[(size_t)EE * 4];        // raw scores, then exp(score - max)
__device__ unsigned g_smax[NN * 4];             // monotonic-uint encoded float max
__device__ float    g_denom[NN * 4];
__device__ int      g_src[EE];
__device__ int      g_dst[EE];

// ---------------- prep: h = x + memory, index load (int32!), softmax init ----------------
__global__ __launch_bounds__(256) void prep_kernel(const int* __restrict__ ei,
                                                   const float* __restrict__ x,
                                                   const float* __restrict__ mem) {
    int i = blockIdx.x * 256 + threadIdx.x;
    if (i < NN * HIDDEN) g_h[i] = x[i] + mem[i];
    if (i < EE) {
        int s = ei[i];
        int d = ei[EE + i];
        // defensive clamp: guarantees no OOB even if layout assumption is wrong
        s = s < 0 ? 0 : (s >= NN ? NN - 1 : s);
        d = d < 0 ? 0 : (d >= NN ? NN - 1 : d);
        g_src[i] = s;
        g_dst[i] = d;
    }
    if (i < NN * 4) {
        g_smax[i]  = 0u;     // encoded "most negative"
        g_denom[i] = 0.0f;
    }
}

// ---------------- SGEMM: C[M,Nc] = A[M,K] @ B[K,Nc] + bias, 128x128 tile, 8x8 microtile ----------------
__global__ __launch_bounds__(256) void sgemm128(const float* __restrict__ A,
                                                const float* __restrict__ B,
                                                const float* __restrict__ bias,
                                                float* __restrict__ C,
                                                int M, int K, int Nc) {
    __shared__ float As[8][128];   // transposed: As[k][m]
    __shared__ float Bs[8][128];   // Bs[k][n]
    int tid  = threadIdx.x;
    int row0 = blockIdx.y * 128;
    int col0 = blockIdx.x * 128;

    int arow = tid >> 1;            // 0..127
    int acol = (tid & 1) * 4;       // 0 or 4
    int brow = tid >> 5;            // 0..7
    int bcol = (tid & 31) * 4;      // 0..124

    int tx = tid & 15;              // col group
    int ty = tid >> 4;              // row group

    float acc[8][8];
#pragma unroll
    for (int i = 0; i < 8; i++)
#pragma unroll
        for (int j = 0; j < 8; j++) acc[i][j] = 0.0f;

    for (int k0 = 0; k0 < K; k0 += 8) {
        float4 av = make_float4(0.f, 0.f, 0.f, 0.f);
        int r = row0 + arow;
        if (r < M) av = *(const float4*)&A[(size_t)r * K + k0 + acol];
        float4 bv = *(const float4*)&B[(size_t)(k0 + brow) * Nc + col0 + bcol];

        __syncthreads();
        As[acol + 0][arow] = av.x;
        As[acol + 1][arow] = av.y;
        As[acol + 2][arow] = av.z;
        As[acol + 3][arow] = av.w;
        *(float4*)&Bs[brow][bcol] = bv;
        __syncthreads();

#pragma unroll
        for (int k = 0; k < 8; k++) {
            float4 a0 = *(const float4*)&As[k][ty * 8];
            float4 a1 = *(const float4*)&As[k][ty * 8 + 4];
            float4 b0 = *(const float4*)&Bs[k][tx * 8];
            float4 b1 = *(const float4*)&Bs[k][tx * 8 + 4];
            float a[8] = {a0.x, a0.y, a0.z, a0.w, a1.x, a1.y, a1.z, a1.w};
            float b[8] = {b0.x, b0.y, b0.z, b0.w, b1.x, b1.y, b1.z, b1.w};
#pragma unroll
            for (int i = 0; i < 8; i++)
#pragma unroll
                for (int j = 0; j < 8; j++) acc[i][j] += a[i] * b[j];
        }
    }

#pragma unroll
    for (int i = 0; i < 8; i++) {
        int r = row0 + ty * 8 + i;
        if (r < M) {
#pragma unroll
            for (int jj = 0; jj < 2; jj++) {
                int c = col0 + tx * 8 + jj * 4;
                float4 bb = bias ? *(const float4*)&bias[c] : make_float4(0.f, 0.f, 0.f, 0.f);
                float4 o;
                o.x = acc[i][jj * 4 + 0] + bb.x;
                o.y = acc[i][jj * 4 + 1] + bb.y;
                o.z = acc[i][jj * 4 + 2] + bb.z;
                o.w = acc[i][jj * 4 + 3] + bb.w;
                *(float4*)&C[(size_t)r * Nc + c] = o;
            }
        }
    }
}

// ---------------- per-edge attention scores + segment max (warp per edge) ----------------
__device__ __forceinline__ unsigned f2ord(float f) {
    unsigned u = __float_as_uint(f);
    return (u & 0x80000000u) ? ~u : (u | 0x80000000u);
}
__device__ __forceinline__ float ord2f(unsigned u) {
    return (u & 0x80000000u) ? __uint_as_float(u ^ 0x80000000u) : __uint_as_float(~u);
}

__global__ __launch_bounds__(256) void scores_kernel() {
    int gw = (blockIdx.x * 256 + threadIdx.x) >> 5;
    if (gw >= EE) return;
    int lane = threadIdx.x & 31;
    int s = g_src[gw], d = g_dst[gw];
    int h   = lane >> 3;                  // head, 8 lanes per head
    int off = h * 64 + (lane & 7) * 8;    // 8 elements per lane
    const float4* qp = (const float4*)&g_q[(size_t)d * HD + off];
    const float4* kp = (const float4*)&g_k[(size_t)s * HD + off];
    float4 q0 = qp[0], q1 = qp[1];
    float4 k0 = kp[0], k1 = kp[1];
    float sc = q0.x * k0.x + q0.y * k0.y + q0.z * k0.z + q0.w * k0.w
             + q1.x * k1.x + q1.y * k1.y + q1.z * k1.z + q1.w * k1.w;
    sc += __shfl_xor_sync(0xffffffffu, sc, 1);
    sc += __shfl_xor_sync(0xffffffffu, sc, 2);
    sc += __shfl_xor_sync(0xffffffffu, sc, 4);
    if ((lane & 7) == 0) {
        sc *= 0.125f;                     // 1/sqrt(64)
        g_e[(size_t)gw * 4 + h] = sc;
        atomicMax(&g_smax[d * 4 + h], f2ord(sc));
    }
}

// ---------------- exp(score - max) + segment denom ----------------
__global__ __launch_bounds__(256) void expdenom_kernel() {
    int i = blockIdx.x * 256 + threadIdx.x;
    if (i >= EE * 4) return;
    int e = i >> 2, h = i & 3;
    int d = g_dst[e];
    float m  = ord2f(g_smax[d * 4 + h]);
    float ex = __expf(g_e[i] - m);
    g_e[i] = ex;
    atomicAdd(&g_denom[d * 4 + h], ex);
}

// ---------------- aggregate: out[dst] += alpha * v[src] (warp per edge) ----------------
__global__ __launch_bounds__(256) void agg_kernel() {
    int gw = (blockIdx.x * 256 + threadIdx.x) >> 5;
    if (gw >= EE) return;
    int lane = threadIdx.x & 31;
    int s = g_src[gw], d = g_dst[gw];
    int h = lane >> 3;
    float ex  = g_e[(size_t)gw * 4 + h];
    float den = g_denom[d * 4 + h];
    float al  = ex / (den + 1e-16f);
    int off = lane * 8;
    const float4* vp = (const float4*)&g_v[(size_t)s * HD + off];
    float4 v0 = vp[0], v1 = vp[1];
    float* op = &g_out[(size_t)d * HD + off];
    atomicAdd(op + 0, al * v0.x);
    atomicAdd(op + 1, al * v0.y);
    atomicAdd(op + 2, al * v0.z);
    atomicAdd(op + 3, al * v0.w);
    atomicAdd(op + 4, al * v1.x);
    atomicAdd(op + 5, al * v1.y);
    atomicAdd(op + 6, al * v1.z);
    atomicAdd(op + 7, al * v1.w);
}

// ---------------- edge MLP: relu(A[src]+B[dst]) -> relu(@W2+b2) -> sigmoid(@W3+b3)*4+1 ----------------
// warp processes 4 edges; W2 resident in smem as float4 [k-chunk][out], FMA-bound.
__global__ __launch_bounds__(256) void mlp_kernel(const float* __restrict__ W2,
                                                  const float* __restrict__ b2,
                                                  const float* __restrict__ W3,
                                                  const float* __restrict__ b3,
                                                  float* __restrict__ outp) {
    __shared__ float4 sW2[32 * 64];       // 32 KB: sW2[c*64+j] = W2[4c..4c+3][j]
    __shared__ float  xs[8][4][128];      // 16 KB: per-warp staging of relu(A+B)
    int tid = threadIdx.x;
    for (int t = tid; t < 2048; t += 256) {
        int c = t >> 6, j = t & 63;
        sW2[t] = make_float4(W2[(4 * c + 0) * 64 + j], W2[(4 * c + 1) * 64 + j],
                             W2[(4 * c + 2) * 64 + j], W2[(4 * c + 3) * 64 + j]);
    }
    __syncthreads();

    int w    = tid >> 5;
    int lane = tid & 31;
    int e0   = (blockIdx.x * 8 + w) * 4;

#pragma unroll
    for (int i = 0; i < 4; i++) {
        int e = e0 + i;
        int s = g_src[e], d = g_dst[e];
        float4 av = *(const float4*)&g_A[(size_t)s * 128 + lane * 4];
        float4 bv = *(const float4*)&g_B[(size_t)d * 128 + lane * 4];
        float4 xv;
        xv.x = fmaxf(av.x + bv.x, 0.f);
        xv.y = fmaxf(av.y + bv.y, 0.f);
        xv.z = fmaxf(av.z + bv.z, 0.f);
        xv.w = fmaxf(av.w + bv.w, 0.f);
        *(float4*)&xs[w][i][lane * 4] = xv;
    }
    __syncwarp();

    float bb0 = b2[lane], bb1 = b2[lane + 32];
    float acc0[4], acc1[4];
#pragma unroll
    for (int i = 0; i < 4; i++) { acc0[i] = bb0; acc1[i] = bb1; }

#pragma unroll
    for (int c = 0; c < 32; c++) {
        float4 w0 = sW2[c * 64 + lane];
        float4 w1 = sW2[c * 64 + lane + 32];
#pragma unroll
        for (int i = 0; i < 4; i++) {
            float4 xv = *(const float4*)&xs[w][i][c * 4];   // broadcast
            acc0[i] += xv.x * w0.x + xv.y * w0.y + xv.z * w0.z + xv.w * w0.w;
            acc1[i] += xv.x * w1.x + xv.y * w1.y + xv.z * w1.z + xv.w * w1.w;
        }
    }

    float w3a = W3[lane], w3b = W3[lane + 32];
    float bb3 = b3[0];
#pragma unroll
    for (int i = 0; i < 4; i++) {
        float h0 = fmaxf(acc0[i], 0.f);
        float h1 = fmaxf(acc1[i], 0.f);
        float p  = h0 * w3a + h1 * w3b;
#pragma unroll
        for (int o = 16; o > 0; o >>= 1) p += __shfl_xor_sync(0xffffffffu, p, o);
        if (lane == 0) outp[e0 + i] = 4.0f / (1.0f + __expf(-(p + bb3))) + 1.0f;
    }
}

// ---------------- launch ----------------
extern "C" void kernel_launch(void* const* d_in, const int* in_sizes, int n_in,
                              void* d_out, int out_size) {
    const int*   ei   = (const int*)d_in[0];     // edge_index is int32 (JAX x64 disabled)
    // d_in[1] = edge_time (unused)
    const float* x    = (const float*)d_in[2];
    const float* mem  = (const float*)d_in[3];
    const float* Wq   = (const float*)d_in[4];
    const float* bq   = (const float*)d_in[5];
    const float* Wk   = (const float*)d_in[6];
    const float* bk   = (const float*)d_in[7];
    const float* Wv   = (const float*)d_in[8];
    const float* bv   = (const float*)d_in[9];
    const float* Wsk  = (const float*)d_in[10];
    const float* bsk  = (const float*)d_in[11];
    const float* W1   = (const float*)d_in[12];
    const float* b1   = (const float*)d_in[13];
    const float* W2   = (const float*)d_in[14];
    const float* b2   = (const float*)d_in[15];
    const float* W3   = (const float*)d_in[16];
    const float* b3   = (const float*)d_in[17];
    float* out = (float*)d_out;

    float *ph, *pq, *pk, *pv, *po, *pA, *pB;
    cudaGetSymbolAddress((void**)&ph, g_h);
    cudaGetSymbolAddress((void**)&pq, g_q);
    cudaGetSymbolAddress((void**)&pk, g_k);
    cudaGetSymbolAddress((void**)&pv, g_v);
    cudaGetSymbolAddress((void**)&po, g_out);
    cudaGetSymbolAddress((void**)&pA, g_A);
    cudaGetSymbolAddress((void**)&pB, g_B);

    prep_kernel<<<50000, 256>>>(ei, x, mem);

    dim3 g256(2, 782);   // 782*128 >= 100000
    dim3 g128(1, 782);
    sgemm128<<<g256, 256>>>(ph, Wq,  bq,  pq, NN, 128, 256);
    sgemm128<<<g256, 256>>>(ph, Wk,  bk,  pk, NN, 128, 256);
    sgemm128<<<g256, 256>>>(ph, Wv,  bv,  pv, NN, 128, 256);
    sgemm128<<<g256, 256>>>(ph, Wsk, bsk, po, NN, 128, 256);

    scores_kernel  <<<50000, 256>>>();
    expdenom_kernel<<<6250, 256>>>();
    agg_kernel     <<<50000, 256>>>();

    sgemm128<<<g128, 256>>>(po, W1,             b1,                  pA, NN, 256, 128);
    sgemm128<<<g128, 256>>>(po, W1 + 256 * 128, (const float*)0,     pB, NN, 256, 128);

    mlp_kernel<<<12500, 256>>>(W2, b2, W3, b3, out);
}

// round 7
// speedup vs baseline: 1.1120x; 1.1120x over previous
#include <cuda_runtime.h>
#include <cuda_bf16.h>
#include <cstdint>

#define NN 100000
#define EE 400000
#define HIDDEN 128
#define HD 256

// ---------------- device scratch ----------------
__device__ __nv_bfloat16 g_hb[(size_t)NN * HIDDEN];    // bf16(x + memory)
__device__ __nv_bfloat16 g_ob[(size_t)NN * HD];        // bf16(out) for GEMM2
__device__ __nv_bfloat16 g_wb[128 * 1024];             // concat bf16 [Wq|Wk|Wv|Wskip]
__device__ __nv_bfloat16 g_w1b[256 * 256];             // concat bf16 [W1a|W1b]
__device__ float    g_bc1[1024];                       // concat bias q|k|v|skip
__device__ float    g_bc2[256];                        // b1 | zeros
__device__ float    g_q[(size_t)NN * HD];
__device__ float    g_k[(size_t)NN * HD];
__device__ float    g_v[(size_t)NN * HD];
__device__ float    g_out[(size_t)NN * HD];            // skip part, then += attention agg
__device__ float    g_A[(size_t)NN * HIDDEN];          // out @ W1a + b1
__device__ float    g_B[(size_t)NN * HIDDEN];          // out @ W1b
__device__ float    g_e[(size_t)EE * 4];
__device__ unsigned g_smax[NN * 4];
__device__ float    g_denom[NN * 4];
__device__ int      g_src[EE];
__device__ int      g_dst[EE];

// ---------------- prep: hb = bf16(x + memory), indices, softmax init ----------------
__global__ __launch_bounds__(256) void prep_kernel(const int* __restrict__ ei,
                                                   const float* __restrict__ x,
                                                   const float* __restrict__ mem) {
    int i = blockIdx.x * 256 + threadIdx.x;
    if (i < NN * HIDDEN) g_hb[i] = __float2bfloat16(x[i] + mem[i]);
    if (i < EE) {
        int s = ei[i];
        int d = ei[EE + i];
        s = s < 0 ? 0 : (s >= NN ? NN - 1 : s);
        d = d < 0 ? 0 : (d >= NN ? NN - 1 : d);
        g_src[i] = s;
        g_dst[i] = d;
    }
    if (i < NN * 4) {
        g_smax[i]  = 0u;
        g_denom[i] = 0.0f;
    }
}

// ---------------- weight/bias conversion & concat ----------------
__global__ __launch_bounds__(256) void wconv_kernel(const float* __restrict__ Wq,
                                                    const float* __restrict__ Wk,
                                                    const float* __restrict__ Wv,
                                                    const float* __restrict__ Wsk,
                                                    const float* __restrict__ W1,
                                                    const float* __restrict__ bq,
                                                    const float* __restrict__ bk,
                                                    const float* __restrict__ bv,
                                                    const float* __restrict__ bsk,
                                                    const float* __restrict__ b1) {
    int i = blockIdx.x * 256 + threadIdx.x;
    if (i < 32768) {                       // 128x256 each
        int r = i >> 8, c = i & 255;
        int o = r * 1024 + c;
        g_wb[o]       = __float2bfloat16(Wq[i]);
        g_wb[o + 256] = __float2bfloat16(Wk[i]);
        g_wb[o + 512] = __float2bfloat16(Wv[i]);
        g_wb[o + 768] = __float2bfloat16(Wsk[i]);
    }
    if (i < 65536) {                       // [256][256] concat of W1 halves
        int k = i >> 8, n = i & 255;
        float v = (n < 128) ? W1[k * 128 + n] : W1[(k + 256) * 128 + (n - 128)];
        g_w1b[i] = __float2bfloat16(v);
    }
    if (i < 256) {
        g_bc1[i]       = bq[i];
        g_bc1[i + 256] = bk[i];
        g_bc1[i + 512] = bv[i];
        g_bc1[i + 768] = bsk[i];
        g_bc2[i] = (i < 128) ? b1[i] : 0.0f;
    }
}

// ---------------- out(fp32) -> bf16 ----------------
__global__ __launch_bounds__(256) void oconv_kernel() {
    int i = blockIdx.x * 256 + threadIdx.x;
    if (i < NN * HD) g_ob[i] = __float2bfloat16(g_out[i]);
}

// ---------------- bf16 tensor-core GEMM: C[M,Nc] = A[M,K] @ B[K,Nc] + bias ----------------
// 128x128 block tile, 8 warps (2x4), warp tile 64x32, mma m16n8k16, double-buffered smem.
// Epilogue routes column group (col >> GSHIFT) to one of 4 destination matrices.
__device__ __forceinline__ void ldsm_x4(uint32_t& r0, uint32_t& r1, uint32_t& r2, uint32_t& r3,
                                        uint32_t addr) {
    asm volatile("ldmatrix.sync.aligned.m8n8.x4.shared.b16 {%0,%1,%2,%3}, [%4];"
                 : "=r"(r0), "=r"(r1), "=r"(r2), "=r"(r3) : "r"(addr));
}
__device__ __forceinline__ void ldsm_x4t(uint32_t& r0, uint32_t& r1, uint32_t& r2, uint32_t& r3,
                                         uint32_t addr) {
    asm volatile("ldmatrix.sync.aligned.m8n8.x4.trans.shared.b16 {%0,%1,%2,%3}, [%4];"
                 : "=r"(r0), "=r"(r1), "=r"(r2), "=r"(r3) : "r"(addr));
}
__device__ __forceinline__ void mma16816(float* c, const uint32_t* a, const uint32_t* b) {
    asm volatile("mma.sync.aligned.m16n8k16.row.col.f32.bf16.bf16.f32 "
                 "{%0,%1,%2,%3}, {%4,%5,%6,%7}, {%8,%9}, {%0,%1,%2,%3};"
                 : "+f"(c[0]), "+f"(c[1]), "+f"(c[2]), "+f"(c[3])
                 : "r"(a[0]), "r"(a[1]), "r"(a[2]), "r"(a[3]), "r"(b[0]), "r"(b[1]));
}

template <int GSHIFT>
__global__ __launch_bounds__(256) void gemm_bf16(const __nv_bfloat16* __restrict__ A,
                                                 const __nv_bfloat16* __restrict__ B,
                                                 const float* __restrict__ bias,
                                                 float* __restrict__ d0, float* __restrict__ d1,
                                                 float* __restrict__ d2, float* __restrict__ d3,
                                                 int M, int K, int Nc) {
    __shared__ __align__(16) __nv_bfloat16 As[2][128][24];   // padded stride 24 (48B)
    __shared__ __align__(16) __nv_bfloat16 Bs[2][16][136];   // padded stride 136 (272B)

    int tid  = threadIdx.x;
    int warp = tid >> 5, lane = tid & 31;
    int wm = (warp >> 2) * 64;
    int wn = (warp & 3) * 32;
    int row0 = blockIdx.y * 128;
    int col0 = blockIdx.x * 128;

    // global load mapping
    int ar = tid >> 1;            // 0..127
    int ac = (tid & 1) * 8;       // 0 or 8
    int br = tid >> 4;            // 0..15
    int bc = (tid & 15) * 8;      // 0..120

    float acc[4][4][4];
#pragma unroll
    for (int i = 0; i < 4; i++)
#pragma unroll
        for (int j = 0; j < 4; j++)
#pragma unroll
            for (int t = 0; t < 4; t++) acc[i][j][t] = 0.0f;

    // preload kt = 0
    {
        int r = row0 + ar;
        uint4 av = make_uint4(0u, 0u, 0u, 0u);
        if (r < M) av = *(const uint4*)&A[(size_t)r * K + ac];
        *(uint4*)&As[0][ar][ac] = av;
        uint4 bv = *(const uint4*)&B[(size_t)br * Nc + col0 + bc];
        *(uint4*)&Bs[0][br][bc] = bv;
    }
    __syncthreads();

    int T = K >> 4;
    for (int kt = 0; kt < T; kt++) {
        int cur = kt & 1, nxt = cur ^ 1;
        bool more = (kt + 1 < T);
        uint4 av, bv;
        if (more) {
            int kk = (kt + 1) << 4;
            int r = row0 + ar;
            av = make_uint4(0u, 0u, 0u, 0u);
            if (r < M) av = *(const uint4*)&A[(size_t)r * K + kk + ac];
            bv = *(const uint4*)&B[(size_t)(kk + br) * Nc + col0 + bc];
        }

        uint32_t afr[4][4];
#pragma unroll
        for (int mi = 0; mi < 4; mi++) {
            int m = wm + mi * 16 + (lane & 15);
            int c = (lane >> 4) * 8;
            uint32_t addr = (uint32_t)__cvta_generic_to_shared(&As[cur][m][c]);
            ldsm_x4(afr[mi][0], afr[mi][1], afr[mi][2], afr[mi][3], addr);
        }
        uint32_t bfr[4][2];
#pragma unroll
        for (int nb = 0; nb < 2; nb++) {
            int k = lane & 15;
            int c = wn + nb * 16 + (lane >> 4) * 8;
            uint32_t addr = (uint32_t)__cvta_generic_to_shared(&Bs[cur][k][c]);
            uint32_t r0, r1, r2, r3;
            ldsm_x4t(r0, r1, r2, r3, addr);
            bfr[nb * 2][0] = r0; bfr[nb * 2][1] = r1;
            bfr[nb * 2 + 1][0] = r2; bfr[nb * 2 + 1][1] = r3;
        }
#pragma unroll
        for (int mi = 0; mi < 4; mi++)
#pragma unroll
            for (int ni = 0; ni < 4; ni++) mma16816(acc[mi][ni], afr[mi], bfr[ni]);

        if (more) {
            *(uint4*)&As[nxt][ar][ac] = av;
            *(uint4*)&Bs[nxt][br][bc] = bv;
            __syncthreads();
        }
    }

    // epilogue: route to destination by column group
    const int GW = 1 << GSHIFT;
#pragma unroll
    for (int mi = 0; mi < 4; mi++) {
#pragma unroll
        for (int ni = 0; ni < 4; ni++) {
            int c = col0 + wn + ni * 8 + (lane & 3) * 2;
            int g = c >> GSHIFT;
            int cl = c & (GW - 1);
            float* dst = (g == 0) ? d0 : (g == 1) ? d1 : (g == 2) ? d2 : d3;
            float2 bb = *(const float2*)&bias[c];
            int r1 = row0 + wm + mi * 16 + (lane >> 2);
            int r2 = r1 + 8;
            if (r1 < M) {
                float2 o = make_float2(acc[mi][ni][0] + bb.x, acc[mi][ni][1] + bb.y);
                *(float2*)&dst[(size_t)r1 * GW + cl] = o;
            }
            if (r2 < M) {
                float2 o = make_float2(acc[mi][ni][2] + bb.x, acc[mi][ni][3] + bb.y);
                *(float2*)&dst[(size_t)r2 * GW + cl] = o;
            }
        }
    }
}

// ---------------- per-edge attention scores + segment max (warp per edge) ----------------
__device__ __forceinline__ unsigned f2ord(float f) {
    unsigned u = __float_as_uint(f);
    return (u & 0x80000000u) ? ~u : (u | 0x80000000u);
}
__device__ __forceinline__ float ord2f(unsigned u) {
    return (u & 0x80000000u) ? __uint_as_float(u ^ 0x80000000u) : __uint_as_float(~u);
}

__global__ __launch_bounds__(256) void scores_kernel() {
    int gw = (blockIdx.x * 256 + threadIdx.x) >> 5;
    if (gw >= EE) return;
    int lane = threadIdx.x & 31;
    int s = g_src[gw], d = g_dst[gw];
    int h   = lane >> 3;
    int off = h * 64 + (lane & 7) * 8;
    const float4* qp = (const float4*)&g_q[(size_t)d * HD + off];
    const float4* kp = (const float4*)&g_k[(size_t)s * HD + off];
    float4 q0 = qp[0], q1 = qp[1];
    float4 k0 = kp[0], k1 = kp[1];
    float sc = q0.x * k0.x + q0.y * k0.y + q0.z * k0.z + q0.w * k0.w
             + q1.x * k1.x + q1.y * k1.y + q1.z * k1.z + q1.w * k1.w;
    sc += __shfl_xor_sync(0xffffffffu, sc, 1);
    sc += __shfl_xor_sync(0xffffffffu, sc, 2);
    sc += __shfl_xor_sync(0xffffffffu, sc, 4);
    if ((lane & 7) == 0) {
        sc *= 0.125f;
        g_e[(size_t)gw * 4 + h] = sc;
        atomicMax(&g_smax[d * 4 + h], f2ord(sc));
    }
}

// ---------------- exp(score - max) + segment denom ----------------
__global__ __launch_bounds__(256) void expdenom_kernel() {
    int i = blockIdx.x * 256 + threadIdx.x;
    if (i >= EE * 4) return;
    int e = i >> 2, h = i & 3;
    int d = g_dst[e];
    float m  = ord2f(g_smax[d * 4 + h]);
    float ex = __expf(g_e[i] - m);
    g_e[i] = ex;
    atomicAdd(&g_denom[d * 4 + h], ex);
}

// ---------------- aggregate: out[dst] += alpha * v[src] (warp per edge) ----------------
__global__ __launch_bounds__(256) void agg_kernel() {
    int gw = (blockIdx.x * 256 + threadIdx.x) >> 5;
    if (gw >= EE) return;
    int lane = threadIdx.x & 31;
    int s = g_src[gw], d = g_dst[gw];
    int h = lane >> 3;
    float ex  = g_e[(size_t)gw * 4 + h];
    float den = g_denom[d * 4 + h];
    float al  = ex / (den + 1e-16f);
    int off = lane * 8;
    const float4* vp = (const float4*)&g_v[(size_t)s * HD + off];
    float4 v0 = vp[0], v1 = vp[1];
    float* op = &g_out[(size_t)d * HD + off];
    atomicAdd(op + 0, al * v0.x);
    atomicAdd(op + 1, al * v0.y);
    atomicAdd(op + 2, al * v0.z);
    atomicAdd(op + 3, al * v0.w);
    atomicAdd(op + 4, al * v1.x);
    atomicAdd(op + 5, al * v1.y);
    atomicAdd(op + 6, al * v1.z);
    atomicAdd(op + 7, al * v1.w);
}

// ---------------- edge MLP head ----------------
__global__ __launch_bounds__(256) void mlp_kernel(const float* __restrict__ W2,
                                                  const float* __restrict__ b2,
                                                  const float* __restrict__ W3,
                                                  const float* __restrict__ b3,
                                                  float* __restrict__ outp) {
    __shared__ float4 sW2[32 * 64];
    __shared__ float  xs[8][4][128];
    int tid = threadIdx.x;
    for (int t = tid; t < 2048; t += 256) {
        int c = t >> 6, j = t & 63;
        sW2[t] = make_float4(W2[(4 * c + 0) * 64 + j], W2[(4 * c + 1) * 64 + j],
                             W2[(4 * c + 2) * 64 + j], W2[(4 * c + 3) * 64 + j]);
    }
    __syncthreads();

    int w    = tid >> 5;
    int lane = tid & 31;
    int e0   = (blockIdx.x * 8 + w) * 4;

#pragma unroll
    for (int i = 0; i < 4; i++) {
        int e = e0 + i;
        int s = g_src[e], d = g_dst[e];
        float4 av = *(const float4*)&g_A[(size_t)s * 128 + lane * 4];
        float4 bv = *(const float4*)&g_B[(size_t)d * 128 + lane * 4];
        float4 xv;
        xv.x = fmaxf(av.x + bv.x, 0.f);
        xv.y = fmaxf(av.y + bv.y, 0.f);
        xv.z = fmaxf(av.z + bv.z, 0.f);
        xv.w = fmaxf(av.w + bv.w, 0.f);
        *(float4*)&xs[w][i][lane * 4] = xv;
    }
    __syncwarp();

    float bb0 = b2[lane], bb1 = b2[lane + 32];
    float acc0[4], acc1[4];
#pragma unroll
    for (int i = 0; i < 4; i++) { acc0[i] = bb0; acc1[i] = bb1; }

#pragma unroll
    for (int c = 0; c < 32; c++) {
        float4 w0 = sW2[c * 64 + lane];
        float4 w1 = sW2[c * 64 + lane + 32];
#pragma unroll
        for (int i = 0; i < 4; i++) {
            float4 xv = *(const float4*)&xs[w][i][c * 4];
            acc0[i] += xv.x * w0.x + xv.y * w0.y + xv.z * w0.z + xv.w * w0.w;
            acc1[i] += xv.x * w1.x + xv.y * w1.y + xv.z * w1.z + xv.w * w1.w;
        }
    }

    float w3a = W3[lane], w3b = W3[lane + 32];
    float bb3 = b3[0];
#pragma unroll
    for (int i = 0; i < 4; i++) {
        float h0 = fmaxf(acc0[i], 0.f);
        float h1 = fmaxf(acc1[i], 0.f);
        float p  = h0 * w3a + h1 * w3b;
#pragma unroll
        for (int o = 16; o > 0; o >>= 1) p += __shfl_xor_sync(0xffffffffu, p, o);
        if (lane == 0) outp[e0 + i] = 4.0f / (1.0f + __expf(-(p + bb3))) + 1.0f;
    }
}

// ---------------- launch ----------------
extern "C" void kernel_launch(void* const* d_in, const int* in_sizes, int n_in,
                              void* d_out, int out_size) {
    const int*   ei   = (const int*)d_in[0];     // int32 (JAX x64 disabled)
    const float* x    = (const float*)d_in[2];
    const float* mem  = (const float*)d_in[3];
    const float* Wq   = (const float*)d_in[4];
    const float* bq   = (const float*)d_in[5];
    const float* Wk   = (const float*)d_in[6];
    const float* bk   = (const float*)d_in[7];
    const float* Wv   = (const float*)d_in[8];
    const float* bv   = (const float*)d_in[9];
    const float* Wsk  = (const float*)d_in[10];
    const float* bsk  = (const float*)d_in[11];
    const float* W1   = (const float*)d_in[12];
    const float* b1   = (const float*)d_in[13];
    const float* W2   = (const float*)d_in[14];
    const float* b2   = (const float*)d_in[15];
    const float* W3   = (const float*)d_in[16];
    const float* b3   = (const float*)d_in[17];
    float* out = (float*)d_out;

    __nv_bfloat16 *phb, *pob, *pwb, *pw1b;
    float *pq, *pk, *pv, *po, *pA, *pB, *pbc1, *pbc2;
    cudaGetSymbolAddress((void**)&phb,  g_hb);
    cudaGetSymbolAddress((void**)&pob,  g_ob);
    cudaGetSymbolAddress((void**)&pwb,  g_wb);
    cudaGetSymbolAddress((void**)&pw1b, g_w1b);
    cudaGetSymbolAddress((void**)&pq,   g_q);
    cudaGetSymbolAddress((void**)&pk,   g_k);
    cudaGetSymbolAddress((void**)&pv,   g_v);
    cudaGetSymbolAddress((void**)&po,   g_out);
    cudaGetSymbolAddress((void**)&pA,   g_A);
    cudaGetSymbolAddress((void**)&pB,   g_B);
    cudaGetSymbolAddress((void**)&pbc1, g_bc1);
    cudaGetSymbolAddress((void**)&pbc2, g_bc2);

    prep_kernel<<<50000, 256>>>(ei, x, mem);
    wconv_kernel<<<256, 256>>>(Wq, Wk, Wv, Wsk, W1, bq, bk, bv, bsk, b1);

    // fused q|k|v|skip GEMM: [100000,128] x [128,1024]
    gemm_bf16<8><<<dim3(8, 782), 256>>>(phb, pwb, pbc1, pq, pk, pv, po, NN, 128, 1024);

    scores_kernel  <<<50000, 256>>>();
    expdenom_kernel<<<6250, 256>>>();
    agg_kernel     <<<50000, 256>>>();

    oconv_kernel<<<100000, 256>>>();
    // fused W1a|W1b GEMM: [100000,256] x [256,256]
    gemm_bf16<7><<<dim3(2, 782), 256>>>(pob, pw1b, pbc2, pA, pB, pB, pB, NN, 256, 256);

    mlp_kernel<<<12500, 256>>>(W2, b2, W3, b3, out);
}

// round 8
// speedup vs baseline: 2.6526x; 2.3854x over previous
#include <cuda_runtime.h>
#include <cuda_bf16.h>
#include <cstdint>

#define NN 100000
#define EE 400000
#define HIDDEN 128
#define HD 256

// ---------------- device scratch ----------------
__device__ __nv_bfloat16 g_hb[(size_t)NN * HIDDEN];    // bf16(x + memory)
__device__ __nv_bfloat16 g_qb[(size_t)NN * HD];
__device__ __nv_bfloat16 g_kb[(size_t)NN * HD];
__device__ __nv_bfloat16 g_vb[(size_t)NN * HD];
__device__ float         g_out[(size_t)NN * HD];       // skip (fp32) from gemm1
__device__ __nv_bfloat16 g_ob[(size_t)NN * HD];        // bf16(skip+agg) for gemm2
__device__ __nv_bfloat16 g_Ab[(size_t)NN * HIDDEN];    // out @ W1a + b1   (bf16)
__device__ __nv_bfloat16 g_Bb[(size_t)NN * HIDDEN];    // out @ W1b        (bf16)
__device__ __nv_bfloat16 g_wb[128 * 1024];             // concat bf16 [Wq|Wk|Wv|Wskip]
__device__ __nv_bfloat16 g_w1b[256 * 256];             // concat bf16 [W1a|W1b]
__device__ float    g_bc1[1024];
__device__ float    g_bc2[256];
__device__ int      g_src[EE];
__device__ int      g_dst[EE];
// CSR by destination
__device__ int      g_deg[NN];
__device__ int      g_cursor[NN];
__device__ int      g_base[NN + 1];
__device__ int      g_csr_src[EE];

__device__ __forceinline__ float2 bf2f(uint32_t u) {
    __nv_bfloat162 b = *reinterpret_cast<__nv_bfloat162*>(&u);
    return __bfloat1622float2(b);
}

// ---------------- prep: hb = bf16(x+mem), indices, zero deg/cursor ----------------
__global__ __launch_bounds__(256) void prep_kernel(const int* __restrict__ ei,
                                                   const float* __restrict__ x,
                                                   const float* __restrict__ mem) {
    int i = blockIdx.x * 256 + threadIdx.x;
    if (i < NN * HIDDEN) g_hb[i] = __float2bfloat16(x[i] + mem[i]);
    if (i < EE) {
        int s = ei[i];
        int d = ei[EE + i];
        s = s < 0 ? 0 : (s >= NN ? NN - 1 : s);
        d = d < 0 ? 0 : (d >= NN ? NN - 1 : d);
        g_src[i] = s;
        g_dst[i] = d;
    }
    if (i < NN) {
        g_deg[i] = 0;
        g_cursor[i] = 0;
    }
}

// ---------------- weight/bias conversion & concat ----------------
__global__ __launch_bounds__(256) void wconv_kernel(const float* __restrict__ Wq,
                                                    const float* __restrict__ Wk,
                                                    const float* __restrict__ Wv,
                                                    const float* __restrict__ Wsk,
                                                    const float* __restrict__ W1,
                                                    const float* __restrict__ bq,
                                                    const float* __restrict__ bk,
                                                    const float* __restrict__ bv,
                                                    const float* __restrict__ bsk,
                                                    const float* __restrict__ b1) {
    int i = blockIdx.x * 256 + threadIdx.x;
    if (i < 32768) {
        int r = i >> 8, c = i & 255;
        int o = r * 1024 + c;
        g_wb[o]       = __float2bfloat16(Wq[i]);
        g_wb[o + 256] = __float2bfloat16(Wk[i]);
        g_wb[o + 512] = __float2bfloat16(Wv[i]);
        g_wb[o + 768] = __float2bfloat16(Wsk[i]);
    }
    if (i < 65536) {
        int k = i >> 8, n = i & 255;
        float v = (n < 128) ? W1[k * 128 + n] : W1[(k + 256) * 128 + (n - 128)];
        g_w1b[i] = __float2bfloat16(v);
    }
    if (i < 256) {
        g_bc1[i]       = bq[i];
        g_bc1[i + 256] = bk[i];
        g_bc1[i + 512] = bv[i];
        g_bc1[i + 768] = bsk[i];
        g_bc2[i] = (i < 128) ? b1[i] : 0.0f;
    }
}

// ---------------- CSR build ----------------
__global__ __launch_bounds__(256) void hist_kernel() {
    int e = blockIdx.x * 256 + threadIdx.x;
    if (e < EE) atomicAdd(&g_deg[g_dst[e]], 1);
}

__global__ __launch_bounds__(1024) void scan_kernel() {
    __shared__ int sh[1024];
    int t = threadIdx.x;
    const int CH = 98;                       // 1024*98 >= 100000
    int beg = t * CH, end = beg + CH;
    if (end > NN) end = NN;
    int s = 0;
    for (int i = beg; i < end; i++) s += g_deg[i];
    sh[t] = s;
    __syncthreads();
    for (int o = 1; o < 1024; o <<= 1) {
        int v = (t >= o) ? sh[t - o] : 0;
        __syncthreads();
        sh[t] += v;
        __syncthreads();
    }
    int run = sh[t] - s;                     // exclusive
    for (int i = beg; i < end; i++) {
        g_base[i] = run;
        run += g_deg[i];
    }
    if (t == 1023) g_base[NN] = sh[1023];
}

__global__ __launch_bounds__(256) void fill_kernel() {
    int e = blockIdx.x * 256 + threadIdx.x;
    if (e >= EE) return;
    int d = g_dst[e];
    int slot = g_base[d] + atomicAdd(&g_cursor[d], 1);
    g_csr_src[slot] = g_src[e];
}

// ---------------- bf16 tensor-core GEMM ----------------
__device__ __forceinline__ void ldsm_x4(uint32_t& r0, uint32_t& r1, uint32_t& r2, uint32_t& r3,
                                        uint32_t addr) {
    asm volatile("ldmatrix.sync.aligned.m8n8.x4.shared.b16 {%0,%1,%2,%3}, [%4];"
                 : "=r"(r0), "=r"(r1), "=r"(r2), "=r"(r3) : "r"(addr));
}
__device__ __forceinline__ void ldsm_x4t(uint32_t& r0, uint32_t& r1, uint32_t& r2, uint32_t& r3,
                                         uint32_t addr) {
    asm volatile("ldmatrix.sync.aligned.m8n8.x4.trans.shared.b16 {%0,%1,%2,%3}, [%4];"
                 : "=r"(r0), "=r"(r1), "=r"(r2), "=r"(r3) : "r"(addr));
}
__device__ __forceinline__ void mma16816(float* c, const uint32_t* a, const uint32_t* b) {
    asm volatile("mma.sync.aligned.m16n8k16.row.col.f32.bf16.bf16.f32 "
                 "{%0,%1,%2,%3}, {%4,%5,%6,%7}, {%8,%9}, {%0,%1,%2,%3};"
                 : "+f"(c[0]), "+f"(c[1]), "+f"(c[2]), "+f"(c[3])
                 : "r"(a[0]), "r"(a[1]), "r"(a[2]), "r"(a[3]), "r"(b[0]), "r"(b[1]));
}

// Groups g < NBF16 are written as bf16, others as fp32.
template <int GSHIFT, int NBF16>
__global__ __launch_bounds__(256) void gemm_bf16(const __nv_bfloat16* __restrict__ A,
                                                 const __nv_bfloat16* __restrict__ B,
                                                 const float* __restrict__ bias,
                                                 void* __restrict__ d0, void* __restrict__ d1,
                                                 void* __restrict__ d2, void* __restrict__ d3,
                                                 int M, int K, int Nc) {
    __shared__ __align__(16) __nv_bfloat16 As[2][128][24];
    __shared__ __align__(16) __nv_bfloat16 Bs[2][16][136];

    int tid  = threadIdx.x;
    int warp = tid >> 5, lane = tid & 31;
    int wm = (warp >> 2) * 64;
    int wn = (warp & 3) * 32;
    int row0 = blockIdx.y * 128;
    int col0 = blockIdx.x * 128;

    int ar = tid >> 1;
    int ac = (tid & 1) * 8;
    int br = tid >> 4;
    int bc = (tid & 15) * 8;

    float acc[4][4][4];
#pragma unroll
    for (int i = 0; i < 4; i++)
#pragma unroll
        for (int j = 0; j < 4; j++)
#pragma unroll
            for (int t = 0; t < 4; t++) acc[i][j][t] = 0.0f;

    {
        int r = row0 + ar;
        uint4 av = make_uint4(0u, 0u, 0u, 0u);
        if (r < M) av = *(const uint4*)&A[(size_t)r * K + ac];
        *(uint4*)&As[0][ar][ac] = av;
        uint4 bv = *(const uint4*)&B[(size_t)br * Nc + col0 + bc];
        *(uint4*)&Bs[0][br][bc] = bv;
    }
    __syncthreads();

    int T = K >> 4;
    for (int kt = 0; kt < T; kt++) {
        int cur = kt & 1, nxt = cur ^ 1;
        bool more = (kt + 1 < T);
        uint4 av, bv;
        if (more) {
            int kk = (kt + 1) << 4;
            int r = row0 + ar;
            av = make_uint4(0u, 0u, 0u, 0u);
            if (r < M) av = *(const uint4*)&A[(size_t)r * K + kk + ac];
            bv = *(const uint4*)&B[(size_t)(kk + br) * Nc + col0 + bc];
        }

        uint32_t afr[4][4];
#pragma unroll
        for (int mi = 0; mi < 4; mi++) {
            int m = wm + mi * 16 + (lane & 15);
            int c = (lane >> 4) * 8;
            uint32_t addr = (uint32_t)__cvta_generic_to_shared(&As[cur][m][c]);
            ldsm_x4(afr[mi][0], afr[mi][1], afr[mi][2], afr[mi][3], addr);
        }
        uint32_t bfr[4][2];
#pragma unroll
        for (int nb = 0; nb < 2; nb++) {
            int k = lane & 15;
            int c = wn + nb * 16 + (lane >> 4) * 8;
            uint32_t addr = (uint32_t)__cvta_generic_to_shared(&Bs[cur][k][c]);
            uint32_t r0, r1, r2, r3;
            ldsm_x4t(r0, r1, r2, r3, addr);
            bfr[nb * 2][0] = r0; bfr[nb * 2][1] = r1;
            bfr[nb * 2 + 1][0] = r2; bfr[nb * 2 + 1][1] = r3;
        }
#pragma unroll
        for (int mi = 0; mi < 4; mi++)
#pragma unroll
            for (int ni = 0; ni < 4; ni++) mma16816(acc[mi][ni], afr[mi], bfr[ni]);

        if (more) {
            *(uint4*)&As[nxt][ar][ac] = av;
            *(uint4*)&Bs[nxt][br][bc] = bv;
            __syncthreads();
        }
    }

    const int GW = 1 << GSHIFT;
#pragma unroll
    for (int mi = 0; mi < 4; mi++) {
#pragma unroll
        for (int ni = 0; ni < 4; ni++) {
            int c = col0 + wn + ni * 8 + (lane & 3) * 2;
            int g = c >> GSHIFT;
            int cl = c & (GW - 1);
            void* dstv = (g == 0) ? d0 : (g == 1) ? d1 : (g == 2) ? d2 : d3;
            float2 bb = *(const float2*)&bias[c];
            int r1 = row0 + wm + mi * 16 + (lane >> 2);
            int r2 = r1 + 8;
            if (g < NBF16) {
                __nv_bfloat16* dp = (__nv_bfloat16*)dstv;
                if (r1 < M) {
                    __nv_bfloat162 p = __floats2bfloat162_rn(acc[mi][ni][0] + bb.x,
                                                             acc[mi][ni][1] + bb.y);
                    *(__nv_bfloat162*)&dp[(size_t)r1 * GW + cl] = p;
                }
                if (r2 < M) {
                    __nv_bfloat162 p = __floats2bfloat162_rn(acc[mi][ni][2] + bb.x,
                                                             acc[mi][ni][3] + bb.y);
                    *(__nv_bfloat162*)&dp[(size_t)r2 * GW + cl] = p;
                }
            } else {
                float* dp = (float*)dstv;
                if (r1 < M) {
                    float2 o = make_float2(acc[mi][ni][0] + bb.x, acc[mi][ni][1] + bb.y);
                    *(float2*)&dp[(size_t)r1 * GW + cl] = o;
                }
                if (r2 < M) {
                    float2 o = make_float2(acc[mi][ni][2] + bb.x, acc[mi][ni][3] + bb.y);
                    *(float2*)&dp[(size_t)r2 * GW + cl] = o;
                }
            }
        }
    }
}

// ---------------- fused attention: warp per dst node, online softmax, no atomics ----------------
__global__ __launch_bounds__(256) void attn_kernel() {
    int node = (blockIdx.x * 256 + threadIdx.x) >> 5;
    if (node >= NN) return;
    int lane = threadIdx.x & 31;
    int off  = lane * 8;                      // this lane's 8 dims; head = lane>>3

    uint4 qv = *(const uint4*)&g_qb[(size_t)node * HD + off];
    float2 q0 = bf2f(qv.x), q1 = bf2f(qv.y), q2 = bf2f(qv.z), q3 = bf2f(qv.w);

    float m = -1e30f, s = 0.0f;
    float acc[8] = {0, 0, 0, 0, 0, 0, 0, 0};

    int beg = g_base[node], end = g_base[node + 1];
    for (int i = beg; i < end; i++) {
        int src = g_csr_src[i];
        uint4 kv = *(const uint4*)&g_kb[(size_t)src * HD + off];
        float2 k0 = bf2f(kv.x), k1 = bf2f(kv.y), k2 = bf2f(kv.z), k3 = bf2f(kv.w);
        float dot = q0.x * k0.x + q0.y * k0.y + q1.x * k1.x + q1.y * k1.y
                  + q2.x * k2.x + q2.y * k2.y + q3.x * k3.x + q3.y * k3.y;
        dot += __shfl_xor_sync(0xffffffffu, dot, 1);
        dot += __shfl_xor_sync(0xffffffffu, dot, 2);
        dot += __shfl_xor_sync(0xffffffffu, dot, 4);
        float sc = dot * 0.125f;              // 1/sqrt(64)

        float nm    = fmaxf(m, sc);
        float scale = __expf(m - nm);
        float e1    = __expf(sc - nm);
        s = s * scale + e1;
        m = nm;

        uint4 vv = *(const uint4*)&g_vb[(size_t)src * HD + off];
        float2 v0 = bf2f(vv.x), v1 = bf2f(vv.y), v2 = bf2f(vv.z), v3 = bf2f(vv.w);
        acc[0] = acc[0] * scale + e1 * v0.x;
        acc[1] = acc[1] * scale + e1 * v0.y;
        acc[2] = acc[2] * scale + e1 * v1.x;
        acc[3] = acc[3] * scale + e1 * v1.y;
        acc[4] = acc[4] * scale + e1 * v2.x;
        acc[5] = acc[5] * scale + e1 * v2.y;
        acc[6] = acc[6] * scale + e1 * v3.x;
        acc[7] = acc[7] * scale + e1 * v3.y;
    }

    float inv = (s > 0.0f) ? 1.0f / s : 0.0f;
    const float4* sk = (const float4*)&g_out[(size_t)node * HD + off];
    float4 s0 = sk[0], s1 = sk[1];
    float o[8];
    o[0] = s0.x + acc[0] * inv;  o[1] = s0.y + acc[1] * inv;
    o[2] = s0.z + acc[2] * inv;  o[3] = s0.w + acc[3] * inv;
    o[4] = s1.x + acc[4] * inv;  o[5] = s1.y + acc[5] * inv;
    o[6] = s1.z + acc[6] * inv;  o[7] = s1.w + acc[7] * inv;

    uint4 ob;
    __nv_bfloat162 p0 = __floats2bfloat162_rn(o[0], o[1]);
    __nv_bfloat162 p1 = __floats2bfloat162_rn(o[2], o[3]);
    __nv_bfloat162 p2 = __floats2bfloat162_rn(o[4], o[5]);
    __nv_bfloat162 p3 = __floats2bfloat162_rn(o[6], o[7]);
    ob.x = *(uint32_t*)&p0; ob.y = *(uint32_t*)&p1;
    ob.z = *(uint32_t*)&p2; ob.w = *(uint32_t*)&p3;
    *(uint4*)&g_ob[(size_t)node * HD + off] = ob;
}

// ---------------- edge MLP head (A,B in bf16) ----------------
__global__ __launch_bounds__(256) void mlp_kernel(const float* __restrict__ W2,
                                                  const float* __restrict__ b2,
                                                  const float* __restrict__ W3,
                                                  const float* __restrict__ b3,
                                                  float* __restrict__ outp) {
    __shared__ float4 sW2[32 * 64];
    __shared__ float  xs[8][4][128];
    int tid = threadIdx.x;
    for (int t = tid; t < 2048; t += 256) {
        int c = t >> 6, j = t & 63;
        sW2[t] = make_float4(W2[(4 * c + 0) * 64 + j], W2[(4 * c + 1) * 64 + j],
                             W2[(4 * c + 2) * 64 + j], W2[(4 * c + 3) * 64 + j]);
    }
    __syncthreads();

    int w    = tid >> 5;
    int lane = tid & 31;
    int e0   = (blockIdx.x * 8 + w) * 4;

#pragma unroll
    for (int i = 0; i < 4; i++) {
        int e = e0 + i;
        int s = g_src[e], d = g_dst[e];
        uint2 au = *(const uint2*)&g_Ab[(size_t)s * 128 + lane * 4];
        uint2 bu = *(const uint2*)&g_Bb[(size_t)d * 128 + lane * 4];
        float2 a0 = bf2f(au.x), a1 = bf2f(au.y);
        float2 c0 = bf2f(bu.x), c1 = bf2f(bu.y);
        float4 xv;
        xv.x = fmaxf(a0.x + c0.x, 0.f);
        xv.y = fmaxf(a0.y + c0.y, 0.f);
        xv.z = fmaxf(a1.x + c1.x, 0.f);
        xv.w = fmaxf(a1.y + c1.y, 0.f);
        *(float4*)&xs[w][i][lane * 4] = xv;
    }
    __syncwarp();

    float bb0 = b2[lane], bb1 = b2[lane + 32];
    float acc0[4], acc1[4];
#pragma unroll
    for (int i = 0; i < 4; i++) { acc0[i] = bb0; acc1[i] = bb1; }

#pragma unroll
    for (int c = 0; c < 32; c++) {
        float4 w0 = sW2[c * 64 + lane];
        float4 w1 = sW2[c * 64 + lane + 32];
#pragma unroll
        for (int i = 0; i < 4; i++) {
            float4 xv = *(const float4*)&xs[w][i][c * 4];
            acc0[i] += xv.x * w0.x + xv.y * w0.y + xv.z * w0.z + xv.w * w0.w;
            acc1[i] += xv.x * w1.x + xv.y * w1.y + xv.z * w1.z + xv.w * w1.w;
        }
    }

    float w3a = W3[lane], w3b = W3[lane + 32];
    float bb3 = b3[0];
#pragma unroll
    for (int i = 0; i < 4; i++) {
        float h0 = fmaxf(acc0[i], 0.f);
        float h1 = fmaxf(acc1[i], 0.f);
        float p  = h0 * w3a + h1 * w3b;
#pragma unroll
        for (int o = 16; o > 0; o >>= 1) p += __shfl_xor_sync(0xffffffffu, p, o);
        if (lane == 0) outp[e0 + i] = 4.0f / (1.0f + __expf(-(p + bb3))) + 1.0f;
    }
}

// ---------------- launch ----------------
extern "C" void kernel_launch(void* const* d_in, const int* in_sizes, int n_in,
                              void* d_out, int out_size) {
    const int*   ei   = (const int*)d_in[0];
    const float* x    = (const float*)d_in[2];
    const float* mem  = (const float*)d_in[3];
    const float* Wq   = (const float*)d_in[4];
    const float* bq   = (const float*)d_in[5];
    const float* Wk   = (const float*)d_in[6];
    const float* bk   = (const float*)d_in[7];
    const float* Wv   = (const float*)d_in[8];
    const float* bv   = (const float*)d_in[9];
    const float* Wsk  = (const float*)d_in[10];
    const float* bsk  = (const float*)d_in[11];
    const float* W1   = (const float*)d_in[12];
    const float* b1   = (const float*)d_in[13];
    const float* W2   = (const float*)d_in[14];
    const float* b2   = (const float*)d_in[15];
    const float* W3   = (const float*)d_in[16];
    const float* b3   = (const float*)d_in[17];
    float* out = (float*)d_out;

    __nv_bfloat16 *phb, *pqb, *pkb, *pvb, *pob, *pAb, *pBb, *pwb, *pw1b;
    float *po, *pbc1, *pbc2;
    cudaGetSymbolAddress((void**)&phb,  g_hb);
    cudaGetSymbolAddress((void**)&pqb,  g_qb);
    cudaGetSymbolAddress((void**)&pkb,  g_kb);
    cudaGetSymbolAddress((void**)&pvb,  g_vb);
    cudaGetSymbolAddress((void**)&pob,  g_ob);
    cudaGetSymbolAddress((void**)&pAb,  g_Ab);
    cudaGetSymbolAddress((void**)&pBb,  g_Bb);
    cudaGetSymbolAddress((void**)&pwb,  g_wb);
    cudaGetSymbolAddress((void**)&pw1b, g_w1b);
    cudaGetSymbolAddress((void**)&po,   g_out);
    cudaGetSymbolAddress((void**)&pbc1, g_bc1);
    cudaGetSymbolAddress((void**)&pbc2, g_bc2);

    prep_kernel<<<50000, 256>>>(ei, x, mem);
    wconv_kernel<<<256, 256>>>(Wq, Wk, Wv, Wsk, W1, bq, bk, bv, bsk, b1);

    // CSR build (independent of GEMM1; stream-ordered)
    hist_kernel<<<1563, 256>>>();
    scan_kernel<<<1, 1024>>>();
    fill_kernel<<<1563, 256>>>();

    // fused q|k|v|skip GEMM: [100000,128] x [128,1024]; q,k,v -> bf16, skip -> fp32
    gemm_bf16<8, 3><<<dim3(8, 782), 256>>>(phb, pwb, pbc1, pqb, pkb, pvb, po, NN, 128, 1024);

    // fused attention (online softmax, no atomics), writes bf16 out
    attn_kernel<<<12500, 256>>>();

    // fused W1a|W1b GEMM: [100000,256] x [256,256]; both halves bf16
    gemm_bf16<7, 4><<<dim3(2, 782), 256>>>(pob, pw1b, pbc2, pAb, pBb, pBb, pBb, NN, 256, 256);

    mlp_kernel<<<12500, 256>>>(W2, b2, W3, b3, out);
}